// round 2
// baseline (speedup 1.0000x reference)
#include <cuda_runtime.h>

#define NGOAL 16384
#define NOBS  65536
#define NTASK 8192
#define NE1   1048576
#define NE2   1048576
#define NB    256
#define FDIM  128
#define SDIM  64

// ---------------- scratch (device globals; no allocation allowed) ----------------
__device__ __align__(16) float g_goalT[NGOAL * SDIM];          // x_goal @ W1            (4 MB)
__device__ __align__(16) float g_acc1[(size_t)NOBS * SDIM];    // x_obs@W1+b1 += edges   (16 MB)
__device__ __align__(16) float g_x1[(size_t)NOBS * SDIM];      // relu(relu(acc1)@W2+b2) (16 MB)
__device__ __align__(16) float g_acc2[NTASK * SDIM];           // x_task += edges        (2 MB)
__device__ __align__(16) float g_x2[NTASK];

// ---------------- GEMM: Y[M,64] = f(X[M,K]) @ W[K,64] (+b) ----------------
// One thread per output row, 64 fp32 accumulators, weights broadcast from smem.
template <int K, bool RELU_IN, bool RELU_OUT, bool BIAS>
__global__ void __launch_bounds__(256) gemm_k(const float* __restrict__ X,
                                              const float* __restrict__ W,
                                              const float* __restrict__ b,
                                              float* __restrict__ Y) {
    __shared__ float Wsh[K * SDIM];
    __shared__ float bsh[SDIM];
    for (int i = threadIdx.x; i < K * SDIM; i += blockDim.x) Wsh[i] = W[i];
    if (threadIdx.x < SDIM) bsh[threadIdx.x] = BIAS ? b[threadIdx.x] : 0.0f;
    __syncthreads();

    const int r = blockIdx.x * blockDim.x + threadIdx.x;
    const float4* Xr = reinterpret_cast<const float4*>(X) + (size_t)r * (K / 4);

    float acc[SDIM];
#pragma unroll
    for (int j = 0; j < SDIM; j++) acc[j] = bsh[j];

#pragma unroll 1
    for (int k4 = 0; k4 < K / 4; k4++) {
        float4 a = Xr[k4];
        if (RELU_IN) {
            a.x = fmaxf(a.x, 0.0f); a.y = fmaxf(a.y, 0.0f);
            a.z = fmaxf(a.z, 0.0f); a.w = fmaxf(a.w, 0.0f);
        }
        const float* w = Wsh + (k4 * 4) * SDIM;
#pragma unroll
        for (int j = 0; j < SDIM; j++) acc[j] = fmaf(a.x, w[j], acc[j]);
        w += SDIM;
#pragma unroll
        for (int j = 0; j < SDIM; j++) acc[j] = fmaf(a.y, w[j], acc[j]);
        w += SDIM;
#pragma unroll
        for (int j = 0; j < SDIM; j++) acc[j] = fmaf(a.z, w[j], acc[j]);
        w += SDIM;
#pragma unroll
        for (int j = 0; j < SDIM; j++) acc[j] = fmaf(a.w, w[j], acc[j]);
    }

    float4* Yr = reinterpret_cast<float4*>(Y) + (size_t)r * (SDIM / 4);
#pragma unroll
    for (int j4 = 0; j4 < SDIM / 4; j4++) {
        float4 o = make_float4(acc[4 * j4], acc[4 * j4 + 1], acc[4 * j4 + 2], acc[4 * j4 + 3]);
        if (RELU_OUT) {
            o.x = fmaxf(o.x, 0.0f); o.y = fmaxf(o.y, 0.0f);
            o.z = fmaxf(o.z, 0.0f); o.w = fmaxf(o.w, 0.0f);
        }
        Yr[j4] = o;
    }
}

// ---------------- edge scatter: out[dst] += table[src], 64-float rows ----------------
// Half-warp per edge (16 lanes x float4 = 64 floats), vector L2 atomics.
__global__ void __launch_bounds__(256) edge_scatter(const int* __restrict__ src,
                                                    const int* __restrict__ dst,
                                                    const float4* __restrict__ table,
                                                    float4* __restrict__ out,
                                                    int npairs) {
    const int gw   = (blockIdx.x * blockDim.x + threadIdx.x) >> 5;
    const int lane = threadIdx.x & 31;
    const int nw   = (gridDim.x * blockDim.x) >> 5;
    const int sub  = lane >> 4;   // which edge of the pair
    const int q    = lane & 15;   // float4 index within the row

    for (int p = gw; p < npairs; p += nw) {
        const int e = p * 2 + sub;
        const int s = __ldg(src + e);
        const int d = __ldg(dst + e);
        float4 v = table[s * 16 + q];
        float4* pd = out + d * 16 + q;
        asm volatile("red.global.add.v4.f32 [%0], {%1,%2,%3,%4};"
                     :: "l"(pd), "f"(v.x), "f"(v.y), "f"(v.z), "f"(v.w)
                     : "memory");
    }
}

// ---------------- acc2 init: copy x_task ----------------
__global__ void copy_f4(const float4* __restrict__ in, float4* __restrict__ out, int n4) {
    int i = blockIdx.x * blockDim.x + threadIdx.x;
    if (i < n4) out[i] = in[i];
}

// ---------------- task head: x2[t] = relu(acc2[t]@W3+b3) @ W4 + b4 ----------------
__global__ void __launch_bounds__(256) task_head(const float* __restrict__ acc2,
                                                 const float* __restrict__ W3,
                                                 const float* __restrict__ b3,
                                                 const float* __restrict__ W4,
                                                 const float* __restrict__ b4,
                                                 float* __restrict__ x2) {
    __shared__ float W3sh[SDIM * SDIM];
    __shared__ float b3sh[SDIM];
    __shared__ float W4sh[SDIM];
    for (int i = threadIdx.x; i < SDIM * SDIM; i += blockDim.x) W3sh[i] = W3[i];
    if (threadIdx.x < SDIM) { b3sh[threadIdx.x] = b3[threadIdx.x]; W4sh[threadIdx.x] = W4[threadIdx.x]; }
    __syncthreads();

    const int warp = threadIdx.x >> 5;
    const int lane = threadIdx.x & 31;
    const int t = blockIdx.x * (blockDim.x >> 5) + warp;

    const float* row = acc2 + (size_t)t * SDIM;
    float s0 = b3sh[lane];
    float s1 = b3sh[lane + 32];
#pragma unroll 4
    for (int k = 0; k < SDIM; k++) {
        float a = __ldg(row + k);  // broadcast within warp
        s0 = fmaf(a, W3sh[k * SDIM + lane], s0);
        s1 = fmaf(a, W3sh[k * SDIM + lane + 32], s1);
    }
    float p = fmaxf(s0, 0.0f) * W4sh[lane] + fmaxf(s1, 0.0f) * W4sh[lane + 32];
#pragma unroll
    for (int o = 16; o; o >>= 1) p += __shfl_xor_sync(0xffffffffu, p, o);
    if (lane == 0) x2[t] = p + b4[0];
}

// ---------------- pooling + critic: one warp per graph (32 tasks, contiguous) ----------------
__global__ void __launch_bounds__(256) pool_critic(const float* __restrict__ x2,
                                                   const float* __restrict__ Wc1,
                                                   const float* __restrict__ bc1,
                                                   const float* __restrict__ Wc2,
                                                   const float* __restrict__ bc2,
                                                   float* __restrict__ out) {
    const int warp = (blockIdx.x * blockDim.x + threadIdx.x) >> 5;
    const int lane = threadIdx.x & 31;
    if (warp >= NB) return;
    float v = x2[warp * 32 + lane];
    float mx = v, sm = v;
#pragma unroll
    for (int o = 16; o; o >>= 1) {
        mx = fmaxf(mx, __shfl_xor_sync(0xffffffffu, mx, o));
        sm += __shfl_xor_sync(0xffffffffu, sm, o);
    }
    if (lane == 0) {
        float mean = sm * (1.0f / 32.0f);
        float r = bc2[0];
#pragma unroll
        for (int i = 0; i < 8; i++) {
            float h = fmaxf(fmaf(mx, Wc1[i], fmaf(mean, Wc1[8 + i], bc1[i])), 0.0f);
            r = fmaf(h, Wc2[i], r);
        }
        out[warp] = r;
    }
}

extern "C" void kernel_launch(void* const* d_in, const int* in_sizes, int n_in,
                              void* d_out, int out_size) {
    const float* x_goal = (const float*)d_in[0];
    const float* x_obs  = (const float*)d_in[1];
    const float* x_task = (const float*)d_in[2];
    const int* ei_go_src = (const int*)d_in[3];
    const int* ei_go_dst = (const int*)d_in[4];
    const int* ei_ot_src = (const int*)d_in[5];
    const int* ei_ot_dst = (const int*)d_in[6];
    // d_in[7] = task_batch (contiguous 32/graph by construction; unused)
    const float* W1  = (const float*)d_in[8];
    const float* b1  = (const float*)d_in[9];
    const float* W2  = (const float*)d_in[10];
    const float* b2  = (const float*)d_in[11];
    const float* W3  = (const float*)d_in[12];
    const float* b3  = (const float*)d_in[13];
    const float* W4  = (const float*)d_in[14];
    const float* b4  = (const float*)d_in[15];
    const float* Wc1 = (const float*)d_in[16];
    const float* bc1 = (const float*)d_in[17];
    const float* Wc2 = (const float*)d_in[18];
    const float* bc2 = (const float*)d_in[19];
    float* out = (float*)d_out;

    float *goalT, *acc1, *x1, *acc2, *x2;
    cudaGetSymbolAddress((void**)&goalT, g_goalT);
    cudaGetSymbolAddress((void**)&acc1, g_acc1);
    cudaGetSymbolAddress((void**)&x1, g_x1);
    cudaGetSymbolAddress((void**)&acc2, g_acc2);
    cudaGetSymbolAddress((void**)&x2, g_x2);

    // 1. goalT = x_goal @ W1   (push W1 through the aggregation: halves edge payload)
    gemm_k<FDIM, false, false, false><<<NGOAL / 256, 256>>>(x_goal, W1, b1, goalT);
    // 2. acc1 = x_obs @ W1 + b1
    gemm_k<FDIM, false, false, true><<<NOBS / 256, 256>>>(x_obs, W1, b1, acc1);
    // 3. acc1[dst] += goalT[src]  over E1 edges
    edge_scatter<<<2048, 256>>>(ei_go_src, ei_go_dst, (const float4*)goalT,
                                (float4*)acc1, NE1 / 2);
    // 4. x1 = relu(relu(acc1) @ W2 + b2)
    gemm_k<SDIM, true, true, true><<<NOBS / 256, 256>>>(acc1, W2, b2, x1);
    // 5. acc2 = x_task
    copy_f4<<<(NTASK * SDIM / 4 + 255) / 256, 256>>>((const float4*)x_task, (float4*)acc2,
                                                     NTASK * SDIM / 4);
    // 6. acc2[dst] += x1[src]  over E2 edges
    edge_scatter<<<2048, 256>>>(ei_ot_src, ei_ot_dst, (const float4*)x1,
                                (float4*)acc2, NE2 / 2);
    // 7. x2[t] = relu(acc2[t]@W3+b3) @ W4 + b4
    task_head<<<NTASK / 8, 256>>>(acc2, W3, b3, W4, b4, x2);
    // 8. per-graph max/mean pool + critic MLP
    pool_critic<<<(NB * 32 + 255) / 256, 256>>>(x2, Wc1, bc1, Wc2, bc2, out);
}

// round 3
// speedup vs baseline: 1.3737x; 1.3737x over previous
#include <cuda_runtime.h>
#include <cstring>

typedef unsigned long long ull;

#define NGOAL 16384
#define NOBS  65536
#define NTASK 8192
#define NE1   1048576
#define NE2   1048576
#define NB    256
#define FDIM  128
#define SDIM  64
#define CAP1  64
#define CAP2  256

// ---------------- scratch (device globals; no allocation allowed) ----------------
__device__ __align__(16) float g_goalT[NGOAL * SDIM];          // x_goal @ W1
__device__ __align__(16) float g_acc1[(size_t)NOBS * SDIM];    // x_obs@W1+b1 + agg
__device__ __align__(16) float g_x1[(size_t)NOBS * SDIM];      // relu(relu(acc1)@W2+b2)
__device__ __align__(16) float g_acc2[NTASK * SDIM];           // x_task + agg
__device__ float g_x2[NTASK];
__device__ int g_deg1[NOBS];
__device__ int g_deg2[NTASK];
__device__ int g_slot1[(size_t)NOBS * CAP1];                   // 16 MB
__device__ int g_slot2[(size_t)NTASK * CAP2];                  // 8 MB

#define FFMA2(d, a, b) \
    asm("fma.rn.f32x2 %0, %1, %2, %0;" : "+l"(d) : "l"(a), "l"(b))

// ================= GEMM: Y[M,64] = f(X[M,K]) @ W[K,64] (+b), packed f32x2 =================
// Block tile: 128 rows x 64 cols, K chunked by 32. 256 threads.
// Thread tile: 8 rows (4 M-pairs at m2 = tm, tm+16, tm+32, tm+48) x 4 cols (4*tn..4*tn+3).
// A in smem k-major as float2 M-pairs (row stride 66 float2 = 132 floats, conflict-free reads).
// W in smem as duplicated pairs Wd[k][j] = (w_kj, w_kj) so FFMA2 pairs across M.
template <int K, bool RELU_IN, bool RELU_OUT, bool BIAS>
__global__ void __launch_bounds__(256) gemm_f2(const float* __restrict__ X,
                                               const float* __restrict__ W,
                                               const float* __restrict__ b,
                                               float* __restrict__ Y) {
    __shared__ float2 As[32][66];   // ~16.9 KB
    __shared__ float2 Wd[32][64];   // 16 KB

    const int tid = threadIdx.x;
    const int tm = tid & 15;
    const int tn = tid >> 4;
    const int m0 = blockIdx.x * 128;

    ull acc[4][4];
#pragma unroll
    for (int c = 0; c < 4; c++) {
        float bv = BIAS ? b[4 * tn + c] : 0.0f;
        float2 bb = make_float2(bv, bv);
        ull bu; memcpy(&bu, &bb, 8);
#pragma unroll
        for (int p = 0; p < 4; p++) acc[p][c] = bu;
    }

    float* Af = (float*)&As[0][0];  // flat view, row k at float offset k*132

    for (int kc = 0; kc < K; kc += 32) {
        __syncthreads();
        // ---- load A chunk: 128 rows x 32 k, transposed into pair-major smem ----
#pragma unroll
        for (int it = 0; it < 4; it++) {
            int idx = tid + 256 * it;
            int m = idx >> 3;       // 0..127
            int f4 = idx & 7;       // k-group 0..7
            float4 v = *(const float4*)(X + (size_t)(m0 + m) * K + kc + 4 * f4);
            if (RELU_IN) {
                v.x = fmaxf(v.x, 0.0f); v.y = fmaxf(v.y, 0.0f);
                v.z = fmaxf(v.z, 0.0f); v.w = fmaxf(v.w, 0.0f);
            }
            Af[(4 * f4 + 0) * 132 + m] = v.x;
            Af[(4 * f4 + 1) * 132 + m] = v.y;
            Af[(4 * f4 + 2) * 132 + m] = v.z;
            Af[(4 * f4 + 3) * 132 + m] = v.w;
        }
        // ---- load W chunk 32x64, duplicated pairs ----
#pragma unroll
        for (int it = 0; it < 2; it++) {
            int idx = tid + 256 * it;   // float4 id over 512
            int k = idx >> 4;
            int j4 = idx & 15;
            float4 w = *(const float4*)(W + (size_t)(kc + k) * 64 + 4 * j4);
            Wd[k][4 * j4 + 0] = make_float2(w.x, w.x);
            Wd[k][4 * j4 + 1] = make_float2(w.y, w.y);
            Wd[k][4 * j4 + 2] = make_float2(w.z, w.z);
            Wd[k][4 * j4 + 3] = make_float2(w.w, w.w);
        }
        __syncthreads();
        // ---- inner product ----
#pragma unroll
        for (int k = 0; k < 32; k++) {
            ull a0 = *(const ull*)&As[k][tm];
            ull a1 = *(const ull*)&As[k][tm + 16];
            ull a2 = *(const ull*)&As[k][tm + 32];
            ull a3 = *(const ull*)&As[k][tm + 48];
            ulonglong2 wA = *(const ulonglong2*)&Wd[k][4 * tn];
            ulonglong2 wB = *(const ulonglong2*)&Wd[k][4 * tn + 2];
            FFMA2(acc[0][0], a0, wA.x); FFMA2(acc[0][1], a0, wA.y);
            FFMA2(acc[0][2], a0, wB.x); FFMA2(acc[0][3], a0, wB.y);
            FFMA2(acc[1][0], a1, wA.x); FFMA2(acc[1][1], a1, wA.y);
            FFMA2(acc[1][2], a1, wB.x); FFMA2(acc[1][3], a1, wB.y);
            FFMA2(acc[2][0], a2, wA.x); FFMA2(acc[2][1], a2, wA.y);
            FFMA2(acc[2][2], a2, wB.x); FFMA2(acc[2][3], a2, wB.y);
            FFMA2(acc[3][0], a3, wA.x); FFMA2(acc[3][1], a3, wA.y);
            FFMA2(acc[3][2], a3, wB.x); FFMA2(acc[3][3], a3, wB.y);
        }
    }

    // ---- epilogue ----
#pragma unroll
    for (int p = 0; p < 4; p++) {
        int r0 = 2 * (tm + 16 * p);
        float2 v[4];
#pragma unroll
        for (int c = 0; c < 4; c++) memcpy(&v[c], &acc[p][c], 8);
        float4 o0 = make_float4(v[0].x, v[1].x, v[2].x, v[3].x);
        float4 o1 = make_float4(v[0].y, v[1].y, v[2].y, v[3].y);
        if (RELU_OUT) {
            o0.x = fmaxf(o0.x, 0.0f); o0.y = fmaxf(o0.y, 0.0f);
            o0.z = fmaxf(o0.z, 0.0f); o0.w = fmaxf(o0.w, 0.0f);
            o1.x = fmaxf(o1.x, 0.0f); o1.y = fmaxf(o1.y, 0.0f);
            o1.z = fmaxf(o1.z, 0.0f); o1.w = fmaxf(o1.w, 0.0f);
        }
        *(float4*)(Y + (size_t)(m0 + r0) * 64 + 4 * tn) = o0;
        *(float4*)(Y + (size_t)(m0 + r0 + 1) * 64 + 4 * tn) = o1;
    }
}

// ================= CSR-bucket build =================
__global__ void zero_deg() {
    int i = blockIdx.x * blockDim.x + threadIdx.x;
    if (i < NOBS) g_deg1[i] = 0;
    else if (i < NOBS + NTASK) g_deg2[i - NOBS] = 0;
}

__global__ void fill_csr(const int* __restrict__ s1, const int* __restrict__ d1,
                         const int* __restrict__ s2, const int* __restrict__ d2) {
    int i = blockIdx.x * blockDim.x + threadIdx.x;
    if (i < NE1) {
        int d = d1[i];
        int p = atomicAdd(&g_deg1[d], 1);
        if (p < CAP1) g_slot1[(size_t)d * CAP1 + p] = s1[i];
    } else {
        int e = i - NE1;
        int d = d2[e];
        int p = atomicAdd(&g_deg2[d], 1);
        if (p < CAP2) g_slot2[(size_t)d * CAP2 + p] = s2[e];
    }
}

// ================= gather: out[d] = base[d] + sum_i table[slot[d][i]] =================
// Half-warp per destination (16 lanes x float4 = 64-float row).
template <int CAP>
__global__ void __launch_bounds__(256) gather(const int* __restrict__ deg,
                                              const int* __restrict__ slot,
                                              const float4* __restrict__ table,
                                              const float4* __restrict__ base,
                                              float4* __restrict__ out) {
    const int hw = (blockIdx.x * blockDim.x + threadIdx.x) >> 4;
    const int q = threadIdx.x & 15;
    const int dg = deg[hw];
    const int* sl = slot + (size_t)hw * CAP;
    float4 v = base[hw * 16 + q];
    for (int i = 0; i < dg; i++) {
        int s = __ldg(sl + i);
        float4 t = table[s * 16 + q];
        v.x += t.x; v.y += t.y; v.z += t.z; v.w += t.w;
    }
    out[hw * 16 + q] = v;
}

// ================= task head: x2[t] = relu(acc2[t]@W3+b3) @ W4 + b4 =================
__global__ void __launch_bounds__(256) task_head(const float* __restrict__ acc2,
                                                 const float* __restrict__ W3,
                                                 const float* __restrict__ b3,
                                                 const float* __restrict__ W4,
                                                 const float* __restrict__ b4,
                                                 float* __restrict__ x2) {
    __shared__ float W3sh[SDIM * SDIM];
    __shared__ float b3sh[SDIM];
    __shared__ float W4sh[SDIM];
    for (int i = threadIdx.x; i < SDIM * SDIM; i += blockDim.x) W3sh[i] = W3[i];
    if (threadIdx.x < SDIM) { b3sh[threadIdx.x] = b3[threadIdx.x]; W4sh[threadIdx.x] = W4[threadIdx.x]; }
    __syncthreads();

    const int warp = threadIdx.x >> 5;
    const int lane = threadIdx.x & 31;
    const int t = blockIdx.x * (blockDim.x >> 5) + warp;

    const float* row = acc2 + (size_t)t * SDIM;
    float s0 = b3sh[lane];
    float s1 = b3sh[lane + 32];
#pragma unroll 4
    for (int k = 0; k < SDIM; k++) {
        float a = __ldg(row + k);
        s0 = fmaf(a, W3sh[k * SDIM + lane], s0);
        s1 = fmaf(a, W3sh[k * SDIM + lane + 32], s1);
    }
    float p = fmaxf(s0, 0.0f) * W4sh[lane] + fmaxf(s1, 0.0f) * W4sh[lane + 32];
#pragma unroll
    for (int o = 16; o; o >>= 1) p += __shfl_xor_sync(0xffffffffu, p, o);
    if (lane == 0) x2[t] = p + b4[0];
}

// ================= pooling + critic: one warp per graph =================
__global__ void __launch_bounds__(256) pool_critic(const float* __restrict__ x2,
                                                   const float* __restrict__ Wc1,
                                                   const float* __restrict__ bc1,
                                                   const float* __restrict__ Wc2,
                                                   const float* __restrict__ bc2,
                                                   float* __restrict__ out) {
    const int warp = (blockIdx.x * blockDim.x + threadIdx.x) >> 5;
    const int lane = threadIdx.x & 31;
    if (warp >= NB) return;
    float v = x2[warp * 32 + lane];
    float mx = v, sm = v;
#pragma unroll
    for (int o = 16; o; o >>= 1) {
        mx = fmaxf(mx, __shfl_xor_sync(0xffffffffu, mx, o));
        sm += __shfl_xor_sync(0xffffffffu, sm, o);
    }
    if (lane == 0) {
        float mean = sm * (1.0f / 32.0f);
        float r = bc2[0];
#pragma unroll
        for (int i = 0; i < 8; i++) {
            float h = fmaxf(fmaf(mx, Wc1[i], fmaf(mean, Wc1[8 + i], bc1[i])), 0.0f);
            r = fmaf(h, Wc2[i], r);
        }
        out[warp] = r;
    }
}

extern "C" void kernel_launch(void* const* d_in, const int* in_sizes, int n_in,
                              void* d_out, int out_size) {
    const float* x_goal = (const float*)d_in[0];
    const float* x_obs  = (const float*)d_in[1];
    const float* x_task = (const float*)d_in[2];
    const int* ei_go_src = (const int*)d_in[3];
    const int* ei_go_dst = (const int*)d_in[4];
    const int* ei_ot_src = (const int*)d_in[5];
    const int* ei_ot_dst = (const int*)d_in[6];
    // d_in[7] = task_batch (contiguous 32/graph; unused)
    const float* W1  = (const float*)d_in[8];
    const float* b1  = (const float*)d_in[9];
    const float* W2  = (const float*)d_in[10];
    const float* b2  = (const float*)d_in[11];
    const float* W3  = (const float*)d_in[12];
    const float* b3  = (const float*)d_in[13];
    const float* W4  = (const float*)d_in[14];
    const float* b4  = (const float*)d_in[15];
    const float* Wc1 = (const float*)d_in[16];
    const float* bc1 = (const float*)d_in[17];
    const float* Wc2 = (const float*)d_in[18];
    const float* bc2 = (const float*)d_in[19];
    float* out = (float*)d_out;

    float *goalT, *acc1, *x1, *acc2, *x2;
    int *deg1, *deg2, *slot1, *slot2;
    cudaGetSymbolAddress((void**)&goalT, g_goalT);
    cudaGetSymbolAddress((void**)&acc1, g_acc1);
    cudaGetSymbolAddress((void**)&x1, g_x1);
    cudaGetSymbolAddress((void**)&acc2, g_acc2);
    cudaGetSymbolAddress((void**)&x2, g_x2);
    cudaGetSymbolAddress((void**)&deg1, g_deg1);
    cudaGetSymbolAddress((void**)&deg2, g_deg2);
    cudaGetSymbolAddress((void**)&slot1, g_slot1);
    cudaGetSymbolAddress((void**)&slot2, g_slot2);

    // --- CSR bucket build (independent of GEMMs) ---
    zero_deg<<<(NOBS + NTASK) / 256, 256>>>();
    fill_csr<<<(NE1 + NE2) / 256, 256>>>(ei_go_src, ei_go_dst, ei_ot_src, ei_ot_dst);

    // --- goalT = x_goal @ W1 (push W1 through aggregation: halves edge payload) ---
    gemm_f2<FDIM, false, false, false><<<NGOAL / 128, 256>>>(x_goal, W1, b1, goalT);
    // --- acc1 = x_obs @ W1 + b1 ---
    gemm_f2<FDIM, false, false, true><<<NOBS / 128, 256>>>(x_obs, W1, b1, acc1);
    // --- acc1[d] += sum goalT[src in bucket(d)] ---
    gather<CAP1><<<NOBS * 16 / 256, 256>>>(deg1, slot1, (const float4*)goalT,
                                           (const float4*)acc1, (float4*)acc1);
    // --- x1 = relu(relu(acc1) @ W2 + b2) ---
    gemm_f2<SDIM, true, true, true><<<NOBS / 128, 256>>>(acc1, W2, b2, x1);
    // --- acc2[d] = x_task[d] + sum x1[src in bucket(d)] ---
    gather<CAP2><<<NTASK * 16 / 256, 256>>>(deg2, slot2, (const float4*)x1,
                                            (const float4*)x_task, (float4*)acc2);
    // --- x2[t] = relu(acc2[t]@W3+b3) @ W4 + b4 ---
    task_head<<<NTASK / 8, 256>>>(acc2, W3, b3, W4, b4, x2);
    // --- per-graph max/mean pool + critic ---
    pool_critic<<<(NB * 32 + 255) / 256, 256>>>(x2, Wc1, bc1, Wc2, bc2, out);
}